// round 2
// baseline (speedup 1.0000x reference)
#include <cuda_runtime.h>
#include <cuda_bf16.h>

#define N_NODES 50000
#define N_EDGES 800000
#define D 64
#define D_OUT 32

// ---------------- scratch (device globals; no allocation allowed) ----------------
__device__ float g_ms0[(size_t)N_NODES * D];   // relation-0 neighbor sums
__device__ float g_ms1[(size_t)N_NODES * D];   // relation-1 neighbor sums
__device__ float g_h1 [(size_t)N_NODES * D];   // layer-1 output
__device__ float g_h2 [(size_t)N_NODES * D];   // layer-2 output
__device__ float g_cnt[2 * N_NODES];           // in-degree per relation (float)
__device__ float g_inv[2 * N_NODES];           // 1/max(cnt,1)

// ---------------- helpers ----------------
__device__ __forceinline__ void red_add_v4(float* p, float4 v) {
    asm volatile("red.global.add.v4.f32 [%0], {%1,%2,%3,%4};"
                 :: "l"(p), "f"(v.x), "f"(v.y), "f"(v.z), "f"(v.w)
                 : "memory");
}
__device__ __forceinline__ void red_add_f32(float* p, float v) {
    asm volatile("red.global.add.f32 [%0], %1;" :: "l"(p), "f"(v) : "memory");
}

// ---------------- degree count: one thread per edge, per relation (grid.y) ----------------
__global__ void count_kernel(const int* __restrict__ ei0, const int* __restrict__ ei1) {
    const int r = blockIdx.y;
    const int* ei = r ? ei1 : ei0;
    int e = blockIdx.x * blockDim.x + threadIdx.x;
    if (e < N_EDGES) {
        int dst = __ldg(ei + N_EDGES + e);
        red_add_f32(&g_cnt[r * N_NODES + dst], 1.0f);
    }
}

__global__ void inv_kernel() {
    int i = blockIdx.x * blockDim.x + threadIdx.x;
    if (i < 2 * N_NODES) g_inv[i] = 1.0f / fmaxf(g_cnt[i], 1.0f);
}

// ---------------- edge scatter: 16 threads/edge, float4 gather + red.add.v4 ----------------
// grid.x = N_EDGES*16/256 (exact), grid.y = relation.
// A warp covers exactly 2 edges; lanes 0 and 16 load the (src,dst) pair, others shuffle.
__global__ void __launch_bounds__(256) scatter_kernel(const float* __restrict__ h,
                                                      const int* __restrict__ ei0,
                                                      const int* __restrict__ ei1) {
    const int r = blockIdx.y;
    const int* ei = r ? ei1 : ei0;
    float* ms = r ? g_ms1 : g_ms0;
    unsigned idx = blockIdx.x * 256u + threadIdx.x;   // < N_EDGES*16 exactly
    int e = idx >> 4;
    int c = (idx & 15) << 2;

    int src, dst;
    if ((threadIdx.x & 15) == 0) {
        src = __ldg(ei + e);
        dst = __ldg(ei + N_EDGES + e);
    }
    src = __shfl_sync(0xFFFFFFFFu, src, (threadIdx.x & 16), 32);
    dst = __shfl_sync(0xFFFFFFFFu, dst, (threadIdx.x & 16), 32);

    float4 v = *reinterpret_cast<const float4*>(h + (size_t)src * D + c);
    red_add_v4(ms + (size_t)dst * D + c, v);
}

// ---------------- fused layer GEMM ----------------
// hout = relu( (ms0*inv0) @ Wl[l,0] + (ms1*inv1) @ Wl[l,1] + hin @ (Wr[l,0]+Wr[l,1]) + bl[l,0]+bl[l,1] )
// Block: 256 threads, tile 128 rows x 64 cols; thread = 8 rows x 4 cols.
// Weights (3 x 64 x 64 fp32 = 48KB) staged in shared; A read straight from global (L2-resident).
__global__ void __launch_bounds__(256, 2) layer_kernel(
    const float* __restrict__ hin,
    const float* __restrict__ ms0,
    const float* __restrict__ ms1,
    const float* __restrict__ Wl,   // layer base: [2][64][64]
    const float* __restrict__ Wr,   // layer base: [2][64][64]
    const float* __restrict__ bl,   // layer base: [2][64]
    float* __restrict__ hout)
{
    __shared__ float Ws[192 * 64];  // 48KB: [0:64)=Wl0, [64:128)=Wl1, [128:192)=Wr0+Wr1
    const int tid = threadIdx.x;

    #pragma unroll
    for (int i = 0; i < 4; i++) {
        int idx = (tid + i * 256) * 4;   // 1024 float4 per 64x64 chunk
        float4 a = *(const float4*)(Wl + idx);
        float4 b = *(const float4*)(Wl + 4096 + idx);
        float4 c = *(const float4*)(Wr + idx);
        float4 d = *(const float4*)(Wr + 4096 + idx);
        *(float4*)(Ws + idx)        = a;
        *(float4*)(Ws + 4096 + idx) = b;
        *(float4*)(Ws + 8192 + idx) = make_float4(c.x + d.x, c.y + d.y, c.z + d.z, c.w + d.w);
    }
    __syncthreads();

    const int c0      = (tid & 15) * 4;
    const int rowBase = blockIdx.x * 128 + (tid >> 4) * 8;

    int rows[8];
    #pragma unroll
    for (int i = 0; i < 8; i++) {
        int r = rowBase + i;
        rows[i] = (r < N_NODES) ? r : (N_NODES - 1);
    }

    float acc[8][4];
    {
        float4 b0 = *(const float4*)(bl + c0);
        float4 b1 = *(const float4*)(bl + 64 + c0);
        float s0 = b0.x + b1.x, s1 = b0.y + b1.y, s2 = b0.z + b1.z, s3 = b0.w + b1.w;
        #pragma unroll
        for (int i = 0; i < 8; i++) { acc[i][0] = s0; acc[i][1] = s1; acc[i][2] = s2; acc[i][3] = s3; }
    }

    // segments 0 and 1: mean-aggregated features, row-scaled by inv after the dot
    #pragma unroll
    for (int s = 0; s < 2; s++) {
        const float* A  = s ? ms1 : ms0;
        const float* iv = g_inv + s * N_NODES;
        const float* Wseg = Ws + s * 4096;

        float tmp[8][4];
        #pragma unroll
        for (int i = 0; i < 8; i++) { tmp[i][0] = 0.f; tmp[i][1] = 0.f; tmp[i][2] = 0.f; tmp[i][3] = 0.f; }

        #pragma unroll 4
        for (int k4 = 0; k4 < 16; k4++) {
            float4 bv0 = *(const float4*)(Wseg + (k4 * 4 + 0) * 64 + c0);
            float4 bv1 = *(const float4*)(Wseg + (k4 * 4 + 1) * 64 + c0);
            float4 bv2 = *(const float4*)(Wseg + (k4 * 4 + 2) * 64 + c0);
            float4 bv3 = *(const float4*)(Wseg + (k4 * 4 + 3) * 64 + c0);
            #pragma unroll
            for (int i = 0; i < 8; i++) {
                float4 av = *(const float4*)(A + (size_t)rows[i] * 64 + k4 * 4);
                tmp[i][0] += av.x * bv0.x + av.y * bv1.x + av.z * bv2.x + av.w * bv3.x;
                tmp[i][1] += av.x * bv0.y + av.y * bv1.y + av.z * bv2.y + av.w * bv3.y;
                tmp[i][2] += av.x * bv0.z + av.y * bv1.z + av.z * bv2.z + av.w * bv3.z;
                tmp[i][3] += av.x * bv0.w + av.y * bv1.w + av.z * bv2.w + av.w * bv3.w;
            }
        }
        #pragma unroll
        for (int i = 0; i < 8; i++) {
            float f = __ldg(iv + rows[i]);
            acc[i][0] += f * tmp[i][0];
            acc[i][1] += f * tmp[i][1];
            acc[i][2] += f * tmp[i][2];
            acc[i][3] += f * tmp[i][3];
        }
    }

    // segment 2: self features through summed Wr
    {
        const float* Wseg = Ws + 8192;
        #pragma unroll 4
        for (int k4 = 0; k4 < 16; k4++) {
            float4 bv0 = *(const float4*)(Wseg + (k4 * 4 + 0) * 64 + c0);
            float4 bv1 = *(const float4*)(Wseg + (k4 * 4 + 1) * 64 + c0);
            float4 bv2 = *(const float4*)(Wseg + (k4 * 4 + 2) * 64 + c0);
            float4 bv3 = *(const float4*)(Wseg + (k4 * 4 + 3) * 64 + c0);
            #pragma unroll
            for (int i = 0; i < 8; i++) {
                float4 av = *(const float4*)(hin + (size_t)rows[i] * 64 + k4 * 4);
                acc[i][0] += av.x * bv0.x + av.y * bv1.x + av.z * bv2.x + av.w * bv3.x;
                acc[i][1] += av.x * bv0.y + av.y * bv1.y + av.z * bv2.y + av.w * bv3.y;
                acc[i][2] += av.x * bv0.z + av.y * bv1.z + av.z * bv2.z + av.w * bv3.z;
                acc[i][3] += av.x * bv0.w + av.y * bv1.w + av.z * bv2.w + av.w * bv3.w;
            }
        }
    }

    #pragma unroll
    for (int i = 0; i < 8; i++) {
        int r = rowBase + i;
        if (r < N_NODES) {
            float4 o;
            o.x = fmaxf(acc[i][0], 0.f);
            o.y = fmaxf(acc[i][1], 0.f);
            o.z = fmaxf(acc[i][2], 0.f);
            o.w = fmaxf(acc[i][3], 0.f);
            *(float4*)(hout + (size_t)r * 64 + c0) = o;
        }
    }
}

// ---------------- final projection: out[N,32] = h2 @ lin_W + lin_b ----------------
// Block: 256 threads, tile 128 rows x 32 cols; thread = 4 rows x 4 cols.
__global__ void __launch_bounds__(256) final_kernel(const float* __restrict__ h,
                                                    const float* __restrict__ W,   // [64][32]
                                                    const float* __restrict__ b,   // [32]
                                                    float* __restrict__ out)
{
    __shared__ float Ws[64 * 32];   // 8KB
    const int tid = threadIdx.x;
    #pragma unroll
    for (int i = 0; i < 2; i++) {
        int idx = (tid + i * 256) * 4;
        *(float4*)(Ws + idx) = *(const float4*)(W + idx);
    }
    __syncthreads();

    const int c0      = (tid & 7) * 4;
    const int rowBase = blockIdx.x * 128 + (tid >> 3) * 4;

    int rows[4];
    #pragma unroll
    for (int i = 0; i < 4; i++) {
        int r = rowBase + i;
        rows[i] = (r < N_NODES) ? r : (N_NODES - 1);
    }

    float4 bv = *(const float4*)(b + c0);
    float acc[4][4];
    #pragma unroll
    for (int i = 0; i < 4; i++) { acc[i][0] = bv.x; acc[i][1] = bv.y; acc[i][2] = bv.z; acc[i][3] = bv.w; }

    #pragma unroll 4
    for (int k4 = 0; k4 < 16; k4++) {
        float4 w0 = *(const float4*)(Ws + (k4 * 4 + 0) * 32 + c0);
        float4 w1 = *(const float4*)(Ws + (k4 * 4 + 1) * 32 + c0);
        float4 w2 = *(const float4*)(Ws + (k4 * 4 + 2) * 32 + c0);
        float4 w3 = *(const float4*)(Ws + (k4 * 4 + 3) * 32 + c0);
        #pragma unroll
        for (int i = 0; i < 4; i++) {
            float4 av = *(const float4*)(h + (size_t)rows[i] * 64 + k4 * 4);
            acc[i][0] += av.x * w0.x + av.y * w1.x + av.z * w2.x + av.w * w3.x;
            acc[i][1] += av.x * w0.y + av.y * w1.y + av.z * w2.y + av.w * w3.y;
            acc[i][2] += av.x * w0.z + av.y * w1.z + av.z * w2.z + av.w * w3.z;
            acc[i][3] += av.x * w0.w + av.y * w1.w + av.z * w2.w + av.w * w3.w;
        }
    }

    #pragma unroll
    for (int i = 0; i < 4; i++) {
        int r = rowBase + i;
        if (r < N_NODES) {
            float4 o = make_float4(acc[i][0], acc[i][1], acc[i][2], acc[i][3]);
            *(float4*)(out + (size_t)r * D_OUT + c0) = o;
        }
    }
}

// ---------------- launch ----------------
extern "C" void kernel_launch(void* const* d_in, const int* in_sizes, int n_in,
                              void* d_out, int out_size) {
    const float* x    = (const float*)d_in[0];   // [50000,64]
    const int*   ei0  = (const int*)  d_in[1];   // [2,800000]
    const int*   ei1  = (const int*)  d_in[2];   // [2,800000]
    const float* Wl   = (const float*)d_in[3];   // [2,2,64,64]
    const float* Wr   = (const float*)d_in[4];   // [2,2,64,64]
    const float* bl   = (const float*)d_in[5];   // [2,2,64]
    const float* linW = (const float*)d_in[6];   // [64,32]
    const float* linb = (const float*)d_in[7];   // [32]
    float* out = (float*)d_out;                  // [50000,32]

    void *p_ms0, *p_ms1, *p_cnt, *p_h1, *p_h2;
    cudaGetSymbolAddress(&p_ms0, g_ms0);
    cudaGetSymbolAddress(&p_ms1, g_ms1);
    cudaGetSymbolAddress(&p_cnt, g_cnt);
    cudaGetSymbolAddress(&p_h1,  g_h1);
    cudaGetSymbolAddress(&p_h2,  g_h2);

    const size_t msBytes = (size_t)N_NODES * D * sizeof(float);
    const int gemmGrid = (N_NODES + 127) / 128;          // 391
    const dim3 cntGrid((N_EDGES + 255) / 256, 2);
    const dim3 scatGrid(N_EDGES * 16 / 256, 2);          // 50000 x 2, exact

    // degrees (shared by both layers)
    cudaMemsetAsync(p_cnt, 0, 2 * N_NODES * sizeof(float));
    count_kernel<<<cntGrid, 256>>>(ei0, ei1);
    inv_kernel<<<(2 * N_NODES + 255) / 256, 256>>>();

    // layer 0
    cudaMemsetAsync(p_ms0, 0, msBytes);
    cudaMemsetAsync(p_ms1, 0, msBytes);
    scatter_kernel<<<scatGrid, 256>>>(x, ei0, ei1);
    layer_kernel<<<gemmGrid, 256>>>(x, (const float*)p_ms0, (const float*)p_ms1,
                                    Wl, Wr, bl, (float*)p_h1);

    // layer 1
    cudaMemsetAsync(p_ms0, 0, msBytes);
    cudaMemsetAsync(p_ms1, 0, msBytes);
    scatter_kernel<<<scatGrid, 256>>>((const float*)p_h1, ei0, ei1);
    layer_kernel<<<gemmGrid, 256>>>((const float*)p_h1, (const float*)p_ms0, (const float*)p_ms1,
                                    Wl + 2 * 64 * 64, Wr + 2 * 64 * 64, bl + 2 * 64, (float*)p_h2);

    // final projection
    final_kernel<<<gemmGrid, 256>>>((const float*)p_h2, linW, linb, out);
}

// round 12
// speedup vs baseline: 1.7036x; 1.7036x over previous
#include <cuda_runtime.h>
#include <cuda_bf16.h>

#define N_NODES 50000
#define N_PAD   50048            // 391 * 128
#define N_EDGES 800000
#define D 64
#define D_OUT 32
#define NBLK_SCAN 196            // 196*256 = 50176 >= N_NODES

// ---------------- scratch (device globals; no allocation allowed) ----------------
__device__ float g_x  [(size_t)N_PAD * D];     // padded copy of input features
__device__ float g_ms0[(size_t)N_PAD * D];     // relation-0 neighbor MEAN
__device__ float g_ms1[(size_t)N_PAD * D];     // relation-1 neighbor MEAN
__device__ float g_h1 [(size_t)N_PAD * D];     // layer-1 output
__device__ float g_h2 [(size_t)N_PAD * D];     // layer-2 output
__device__ int   g_deg   [2 * N_NODES];        // in-degree per relation
__device__ int   g_rowptr[2 * (N_NODES + 1)];  // CSR row pointers per relation
__device__ int   g_cursor[2 * N_NODES];        // fill cursors
__device__ int   g_adj0  [N_EDGES];            // src lists (CSR by dst), relation 0
__device__ int   g_adj1  [N_EDGES];            // relation 1
__device__ int   g_bsum  [2 * NBLK_SCAN];      // per-block degree sums
__device__ int   g_boff  [2 * NBLK_SCAN];      // exclusive block offsets

// ---------------- degree histogram: 1 thread/edge ----------------
__global__ void deg_count_kernel(const int* __restrict__ ei0, const int* __restrict__ ei1) {
    const int r = blockIdx.y;
    const int* ei = r ? ei1 : ei0;
    int e = blockIdx.x * 256 + threadIdx.x;           // grid.x = 3125 -> exact
    int dst = __ldg(ei + N_EDGES + e);
    atomicAdd(&g_deg[r * N_NODES + dst], 1);
}

// ---------------- scan step 1: per-block reduce of degrees ----------------
__global__ void block_reduce_kernel() {
    __shared__ int sh[256];
    const int r = blockIdx.y;
    int i = blockIdx.x * 256 + threadIdx.x;
    int v = (i < N_NODES) ? g_deg[r * N_NODES + i] : 0;
    sh[threadIdx.x] = v;
    __syncthreads();
    #pragma unroll
    for (int off = 128; off > 0; off >>= 1) {
        if (threadIdx.x < off) sh[threadIdx.x] += sh[threadIdx.x + off];
        __syncthreads();
    }
    if (threadIdx.x == 0) g_bsum[r * NBLK_SCAN + blockIdx.x] = sh[0];
}

// ---------------- scan step 2: scan the block sums (single block) ----------------
__global__ void scan_bsums_kernel() {
    __shared__ int sh[256];
    int t = threadIdx.x;
    for (int r = 0; r < 2; r++) {
        int v = (t < NBLK_SCAN) ? g_bsum[r * NBLK_SCAN + t] : 0;
        sh[t] = v;
        __syncthreads();
        #pragma unroll
        for (int off = 1; off < 256; off <<= 1) {
            int u = (t >= off) ? sh[t - off] : 0;
            __syncthreads();
            sh[t] += u;
            __syncthreads();
        }
        if (t < NBLK_SCAN) g_boff[r * NBLK_SCAN + t] = sh[t] - v;   // exclusive
        __syncthreads();
    }
}

// ---------------- scan step 3: per-block exclusive scan + offsets -> rowptr, cursor ----------------
__global__ void finalize_scan_kernel() {
    __shared__ int sh[256];
    const int r = blockIdx.y;
    int t = threadIdx.x;
    int i = blockIdx.x * 256 + t;
    int v = (i < N_NODES) ? g_deg[r * N_NODES + i] : 0;
    sh[t] = v;
    __syncthreads();
    #pragma unroll
    for (int off = 1; off < 256; off <<= 1) {
        int u = (t >= off) ? sh[t - off] : 0;
        __syncthreads();
        sh[t] += u;
        __syncthreads();
    }
    int excl = sh[t] - v + g_boff[r * NBLK_SCAN + blockIdx.x];
    if (i < N_NODES) {
        g_rowptr[r * (N_NODES + 1) + i] = excl;
        g_cursor[r * N_NODES + i]       = excl;
    }
    if (blockIdx.x == 0 && t == 0) g_rowptr[r * (N_NODES + 1) + N_NODES] = N_EDGES;
}

// ---------------- CSR fill: scatter src ids into dst buckets ----------------
__global__ void fill_kernel(const int* __restrict__ ei0, const int* __restrict__ ei1) {
    const int r = blockIdx.y;
    const int* ei = r ? ei1 : ei0;
    int* adj = r ? g_adj1 : g_adj0;
    int e = blockIdx.x * 256 + threadIdx.x;           // exact
    int src = __ldg(ei + e);
    int dst = __ldg(ei + N_EDGES + e);
    int pos = atomicAdd(&g_cursor[r * N_NODES + dst], 1);
    adj[pos] = src;
}

// ---------------- mean gather: 16 threads per node, both relations via grid.y ----------------
__global__ void __launch_bounds__(256) gather_kernel(const float* __restrict__ h) {
    const int r = blockIdx.y;
    const int* __restrict__ adj = r ? g_adj1 : g_adj0;
    float* __restrict__ ms = r ? g_ms1 : g_ms0;
    const int* __restrict__ rp = g_rowptr + r * (N_NODES + 1);

    int group = threadIdx.x >> 4;                      // 0..15
    int lane  = threadIdx.x & 15;
    int node  = blockIdx.x * 16 + group;               // grid.x = 3125 -> exact 50000

    int beg = __ldg(rp + node);
    int end = __ldg(rp + node + 1);

    float4 acc = make_float4(0.f, 0.f, 0.f, 0.f);
    int j = beg;
    // unroll-4 over neighbors for MLP
    for (; j + 4 <= end; j += 4) {
        int s0 = __ldg(adj + j + 0);
        int s1 = __ldg(adj + j + 1);
        int s2 = __ldg(adj + j + 2);
        int s3 = __ldg(adj + j + 3);
        float4 v0 = *(const float4*)(h + (size_t)s0 * D + lane * 4);
        float4 v1 = *(const float4*)(h + (size_t)s1 * D + lane * 4);
        float4 v2 = *(const float4*)(h + (size_t)s2 * D + lane * 4);
        float4 v3 = *(const float4*)(h + (size_t)s3 * D + lane * 4);
        acc.x += v0.x + v1.x + v2.x + v3.x;
        acc.y += v0.y + v1.y + v2.y + v3.y;
        acc.z += v0.z + v1.z + v2.z + v3.z;
        acc.w += v0.w + v1.w + v2.w + v3.w;
    }
    for (; j < end; j++) {
        int s = __ldg(adj + j);
        float4 v = *(const float4*)(h + (size_t)s * D + lane * 4);
        acc.x += v.x; acc.y += v.y; acc.z += v.z; acc.w += v.w;
    }

    int deg = end - beg;
    float iv = 1.0f / (float)(deg > 0 ? deg : 1);
    float4 o = make_float4(acc.x * iv, acc.y * iv, acc.z * iv, acc.w * iv);
    *(float4*)(ms + (size_t)node * D + lane * 4) = o;
}

// ---------------- fused layer GEMM ----------------
// hout = relu( mean0 @ Wl[l,0] + mean1 @ Wl[l,1] + hin @ (Wr[l,0]+Wr[l,1]) + bl[l,0]+bl[l,1] )
// Block 256 threads, tile 128x64; thread = 8 rows x 4 cols. All buffers padded to N_PAD rows.
__global__ void __launch_bounds__(256, 3) layer_kernel(
    const float* __restrict__ hin,
    const float* __restrict__ m0,
    const float* __restrict__ m1,
    const float* __restrict__ Wl,   // layer base: [2][64][64]
    const float* __restrict__ Wr,   // layer base: [2][64][64]
    const float* __restrict__ bl,   // layer base: [2][64]
    float* __restrict__ hout)
{
    __shared__ float Ws[192 * 64];  // 48KB: [0:64)=Wl0, [64:128)=Wl1, [128:192)=Wr0+Wr1
    const int tid = threadIdx.x;

    #pragma unroll
    for (int i = 0; i < 4; i++) {
        int idx = (tid + i * 256) * 4;
        float4 a = *(const float4*)(Wl + idx);
        float4 b = *(const float4*)(Wl + 4096 + idx);
        float4 c = *(const float4*)(Wr + idx);
        float4 d = *(const float4*)(Wr + 4096 + idx);
        *(float4*)(Ws + idx)        = a;
        *(float4*)(Ws + 4096 + idx) = b;
        *(float4*)(Ws + 8192 + idx) = make_float4(c.x + d.x, c.y + d.y, c.z + d.z, c.w + d.w);
    }
    __syncthreads();

    const int c0      = (tid & 15) * 4;
    const int rowBase = blockIdx.x * 128 + (tid >> 4) * 8;

    float acc[8][4];
    {
        float4 b0 = *(const float4*)(bl + c0);
        float4 b1 = *(const float4*)(bl + 64 + c0);
        float s0 = b0.x + b1.x, s1 = b0.y + b1.y, s2 = b0.z + b1.z, s3 = b0.w + b1.w;
        #pragma unroll
        for (int i = 0; i < 8; i++) { acc[i][0] = s0; acc[i][1] = s1; acc[i][2] = s2; acc[i][3] = s3; }
    }

    #pragma unroll
    for (int s = 0; s < 3; s++) {
        const float* A = (s == 0) ? m0 : (s == 1) ? m1 : hin;
        const float* Arow = A + (size_t)rowBase * D;
        const float* Wseg = Ws + s * 4096;

        #pragma unroll 1
        for (int k4 = 0; k4 < 16; k4++) {
            float4 bv0 = *(const float4*)(Wseg + (k4 * 4 + 0) * 64 + c0);
            float4 bv1 = *(const float4*)(Wseg + (k4 * 4 + 1) * 64 + c0);
            float4 bv2 = *(const float4*)(Wseg + (k4 * 4 + 2) * 64 + c0);
            float4 bv3 = *(const float4*)(Wseg + (k4 * 4 + 3) * 64 + c0);
            #pragma unroll
            for (int i = 0; i < 8; i++) {
                float4 av = *(const float4*)(Arow + i * D + k4 * 4);
                acc[i][0] += av.x * bv0.x + av.y * bv1.x + av.z * bv2.x + av.w * bv3.x;
                acc[i][1] += av.x * bv0.y + av.y * bv1.y + av.z * bv2.y + av.w * bv3.y;
                acc[i][2] += av.x * bv0.z + av.y * bv1.z + av.z * bv2.z + av.w * bv3.z;
                acc[i][3] += av.x * bv0.w + av.y * bv1.w + av.z * bv2.w + av.w * bv3.w;
            }
        }
    }

    float* orow = hout + (size_t)rowBase * D + c0;
    #pragma unroll
    for (int i = 0; i < 8; i++) {
        float4 o;
        o.x = fmaxf(acc[i][0], 0.f);
        o.y = fmaxf(acc[i][1], 0.f);
        o.z = fmaxf(acc[i][2], 0.f);
        o.w = fmaxf(acc[i][3], 0.f);
        *(float4*)(orow + i * D) = o;
    }
}

// ---------------- final projection: out[N,32] = h2 @ lin_W + lin_b ----------------
__global__ void __launch_bounds__(256) final_kernel(const float* __restrict__ h,
                                                    const float* __restrict__ W,   // [64][32]
                                                    const float* __restrict__ b,   // [32]
                                                    float* __restrict__ out)
{
    __shared__ float Ws[64 * 32];   // 8KB
    const int tid = threadIdx.x;
    #pragma unroll
    for (int i = 0; i < 2; i++) {
        int idx = (tid + i * 256) * 4;
        *(float4*)(Ws + idx) = *(const float4*)(W + idx);
    }
    __syncthreads();

    const int c0      = (tid & 7) * 4;
    const int rowBase = blockIdx.x * 128 + (tid >> 3) * 4;
    const float* hrow = h + (size_t)rowBase * D;

    float4 bv = *(const float4*)(b + c0);
    float acc[4][4];
    #pragma unroll
    for (int i = 0; i < 4; i++) { acc[i][0] = bv.x; acc[i][1] = bv.y; acc[i][2] = bv.z; acc[i][3] = bv.w; }

    #pragma unroll 4
    for (int k4 = 0; k4 < 16; k4++) {
        float4 w0 = *(const float4*)(Ws + (k4 * 4 + 0) * 32 + c0);
        float4 w1 = *(const float4*)(Ws + (k4 * 4 + 1) * 32 + c0);
        float4 w2 = *(const float4*)(Ws + (k4 * 4 + 2) * 32 + c0);
        float4 w3 = *(const float4*)(Ws + (k4 * 4 + 3) * 32 + c0);
        #pragma unroll
        for (int i = 0; i < 4; i++) {
            float4 av = *(const float4*)(hrow + i * D + k4 * 4);
            acc[i][0] += av.x * w0.x + av.y * w1.x + av.z * w2.x + av.w * w3.x;
            acc[i][1] += av.x * w0.y + av.y * w1.y + av.z * w2.y + av.w * w3.y;
            acc[i][2] += av.x * w0.z + av.y * w1.z + av.z * w2.z + av.w * w3.z;
            acc[i][3] += av.x * w0.w + av.y * w1.w + av.z * w2.w + av.w * w3.w;
        }
    }

    #pragma unroll
    for (int i = 0; i < 4; i++) {
        int r = rowBase + i;
        if (r < N_NODES) {
            float4 o = make_float4(acc[i][0], acc[i][1], acc[i][2], acc[i][3]);
            *(float4*)(out + (size_t)r * D_OUT + c0) = o;
        }
    }
}

// ---------------- launch ----------------
extern "C" void kernel_launch(void* const* d_in, const int* in_sizes, int n_in,
                              void* d_out, int out_size) {
    const float* x    = (const float*)d_in[0];   // [50000,64]
    const int*   ei0  = (const int*)  d_in[1];   // [2,800000]
    const int*   ei1  = (const int*)  d_in[2];   // [2,800000]
    const float* Wl   = (const float*)d_in[3];   // [2,2,64,64]
    const float* Wr   = (const float*)d_in[4];   // [2,2,64,64]
    const float* bl   = (const float*)d_in[5];   // [2,2,64]
    const float* linW = (const float*)d_in[6];   // [64,32]
    const float* linb = (const float*)d_in[7];   // [32]
    float* out = (float*)d_out;                  // [50000,32]

    void *p_x, *p_ms0, *p_ms1, *p_h1, *p_h2, *p_deg;
    cudaGetSymbolAddress(&p_x,   g_x);
    cudaGetSymbolAddress(&p_ms0, g_ms0);
    cudaGetSymbolAddress(&p_ms1, g_ms1);
    cudaGetSymbolAddress(&p_h1,  g_h1);
    cudaGetSymbolAddress(&p_h2,  g_h2);
    cudaGetSymbolAddress(&p_deg, g_deg);

    const int gemmGrid = N_PAD / 128;                  // 391
    const dim3 edgeGrid(N_EDGES / 256, 2);             // 3125 x 2, exact
    const dim3 scanGrid(NBLK_SCAN, 2);
    const dim3 gatherGrid(N_NODES / 16, 2);            // 3125 x 2, exact

    // padded input copy
    cudaMemcpyAsync(p_x, x, (size_t)N_NODES * D * sizeof(float), cudaMemcpyDeviceToDevice);

    // CSR build (once; shared by both layers)
    cudaMemsetAsync(p_deg, 0, 2 * N_NODES * sizeof(int));
    deg_count_kernel<<<edgeGrid, 256>>>(ei0, ei1);
    block_reduce_kernel<<<scanGrid, 256>>>();
    scan_bsums_kernel<<<1, 256>>>();
    finalize_scan_kernel<<<scanGrid, 256>>>();
    fill_kernel<<<edgeGrid, 256>>>(ei0, ei1);

    // layer 0
    gather_kernel<<<gatherGrid, 256>>>((const float*)p_x);
    layer_kernel<<<gemmGrid, 256>>>((const float*)p_x, (const float*)p_ms0, (const float*)p_ms1,
                                    Wl, Wr, bl, (float*)p_h1);

    // layer 1
    gather_kernel<<<gatherGrid, 256>>>((const float*)p_h1);
    layer_kernel<<<gemmGrid, 256>>>((const float*)p_h1, (const float*)p_ms0, (const float*)p_ms1,
                                    Wl + 2 * 64 * 64, Wr + 2 * 64 * 64, bl + 2 * 64, (float*)p_h2);

    // final projection
    final_kernel<<<gemmGrid, 256>>>((const float*)p_h2, linW, linb, out);
}

// round 17
// speedup vs baseline: 1.8479x; 1.0847x over previous
#include <cuda_runtime.h>
#include <cuda_fp16.h>

#define N_NODES 50000
#define N_PAD   50048            // 391 * 128
#define N_EDGES 800000
#define D 64
#define D_OUT 32
#define NBLK_SCAN 196            // 196*256 = 50176 >= N_NODES

// ---------------- scratch (device globals; no allocation allowed) ----------------
__device__ __half g_xh[(size_t)N_PAD * D];     // fp16 copy of input features (pad rows stay 0)
__device__ __half g_h1[(size_t)N_PAD * D];     // layer-1 output, fp16
__device__ float  g_ms0[(size_t)N_PAD * D];    // relation-0 neighbor MEAN (fp32)
__device__ float  g_ms1[(size_t)N_PAD * D];    // relation-1 neighbor MEAN (fp32)
__device__ int    g_deg   [2 * N_NODES];
__device__ int    g_rowptr[2 * (N_NODES + 1)];
__device__ int    g_cursor[2 * N_NODES];
__device__ int    g_adj0  [N_EDGES];
__device__ int    g_adj1  [N_EDGES];
__device__ int    g_bsum  [2 * NBLK_SCAN];
__device__ int    g_boff  [2 * NBLK_SCAN];

// ---------------- x fp32 -> fp16 (exact grid: 3125*256 float4 groups) ----------------
__global__ void cvt_x_kernel(const float* __restrict__ x) {
    int i = blockIdx.x * 256 + threadIdx.x;            // < 800000, exact
    float4 v = *(const float4*)(x + (size_t)i * 4);
    __half2 a = __floats2half2_rn(v.x, v.y);
    __half2 b = __floats2half2_rn(v.z, v.w);
    uint2 u;
    u.x = *reinterpret_cast<unsigned int*>(&a);
    u.y = *reinterpret_cast<unsigned int*>(&b);
    *reinterpret_cast<uint2*>(g_xh + (size_t)i * 4) = u;
}

// ---------------- degree histogram: 1 thread/edge ----------------
__global__ void deg_count_kernel(const int* __restrict__ ei0, const int* __restrict__ ei1) {
    const int r = blockIdx.y;
    const int* ei = r ? ei1 : ei0;
    int e = blockIdx.x * 256 + threadIdx.x;            // exact
    int dst = __ldg(ei + N_EDGES + e);
    atomicAdd(&g_deg[r * N_NODES + dst], 1);
}

// ---------------- scan step 1 ----------------
__global__ void block_reduce_kernel() {
    __shared__ int sh[256];
    const int r = blockIdx.y;
    int i = blockIdx.x * 256 + threadIdx.x;
    int v = (i < N_NODES) ? g_deg[r * N_NODES + i] : 0;
    sh[threadIdx.x] = v;
    __syncthreads();
    #pragma unroll
    for (int off = 128; off > 0; off >>= 1) {
        if (threadIdx.x < off) sh[threadIdx.x] += sh[threadIdx.x + off];
        __syncthreads();
    }
    if (threadIdx.x == 0) g_bsum[r * NBLK_SCAN + blockIdx.x] = sh[0];
}

// ---------------- scan step 2 ----------------
__global__ void scan_bsums_kernel() {
    __shared__ int sh[256];
    int t = threadIdx.x;
    for (int r = 0; r < 2; r++) {
        int v = (t < NBLK_SCAN) ? g_bsum[r * NBLK_SCAN + t] : 0;
        sh[t] = v;
        __syncthreads();
        #pragma unroll
        for (int off = 1; off < 256; off <<= 1) {
            int u = (t >= off) ? sh[t - off] : 0;
            __syncthreads();
            sh[t] += u;
            __syncthreads();
        }
        if (t < NBLK_SCAN) g_boff[r * NBLK_SCAN + t] = sh[t] - v;
        __syncthreads();
    }
}

// ---------------- scan step 3 ----------------
__global__ void finalize_scan_kernel() {
    __shared__ int sh[256];
    const int r = blockIdx.y;
    int t = threadIdx.x;
    int i = blockIdx.x * 256 + t;
    int v = (i < N_NODES) ? g_deg[r * N_NODES + i] : 0;
    sh[t] = v;
    __syncthreads();
    #pragma unroll
    for (int off = 1; off < 256; off <<= 1) {
        int u = (t >= off) ? sh[t - off] : 0;
        __syncthreads();
        sh[t] += u;
        __syncthreads();
    }
    int excl = sh[t] - v + g_boff[r * NBLK_SCAN + blockIdx.x];
    if (i < N_NODES) {
        g_rowptr[r * (N_NODES + 1) + i] = excl;
        g_cursor[r * N_NODES + i]       = excl;
    }
    if (blockIdx.x == 0 && t == 0) g_rowptr[r * (N_NODES + 1) + N_NODES] = N_EDGES;
}

// ---------------- CSR fill ----------------
__global__ void fill_kernel(const int* __restrict__ ei0, const int* __restrict__ ei1) {
    const int r = blockIdx.y;
    const int* ei = r ? ei1 : ei0;
    int* adj = r ? g_adj1 : g_adj0;
    int e = blockIdx.x * 256 + threadIdx.x;            // exact
    int src = __ldg(ei + e);
    int dst = __ldg(ei + N_EDGES + e);
    int pos = atomicAdd(&g_cursor[r * N_NODES + dst], 1);
    adj[pos] = src;
}

// ---------------- mean gather from fp16 features: 16 threads/node ----------------
__device__ __forceinline__ void acc_half4(float4& acc, const __half* p) {
    uint2 u = *reinterpret_cast<const uint2*>(p);
    __half2 h01 = *reinterpret_cast<__half2*>(&u.x);
    __half2 h23 = *reinterpret_cast<__half2*>(&u.y);
    float2 f01 = __half22float2(h01);
    float2 f23 = __half22float2(h23);
    acc.x += f01.x; acc.y += f01.y; acc.z += f23.x; acc.w += f23.y;
}

__global__ void __launch_bounds__(256) gather_kernel(const __half* __restrict__ h) {
    const int r = blockIdx.y;
    const int* __restrict__ adj = r ? g_adj1 : g_adj0;
    float* __restrict__ ms = r ? g_ms1 : g_ms0;
    const int* __restrict__ rp = g_rowptr + r * (N_NODES + 1);

    int group = threadIdx.x >> 4;
    int lane  = threadIdx.x & 15;
    int node  = blockIdx.x * 16 + group;               // exact 50000

    int beg = __ldg(rp + node);
    int end = __ldg(rp + node + 1);

    float4 acc = make_float4(0.f, 0.f, 0.f, 0.f);
    int j = beg;
    for (; j + 4 <= end; j += 4) {
        int s0 = __ldg(adj + j + 0);
        int s1 = __ldg(adj + j + 1);
        int s2 = __ldg(adj + j + 2);
        int s3 = __ldg(adj + j + 3);
        acc_half4(acc, h + (size_t)s0 * D + lane * 4);
        acc_half4(acc, h + (size_t)s1 * D + lane * 4);
        acc_half4(acc, h + (size_t)s2 * D + lane * 4);
        acc_half4(acc, h + (size_t)s3 * D + lane * 4);
    }
    for (; j < end; j++) {
        int s = __ldg(adj + j);
        acc_half4(acc, h + (size_t)s * D + lane * 4);
    }

    int deg = end - beg;
    float iv = 1.0f / (float)(deg > 0 ? deg : 1);
    float4 o = make_float4(acc.x * iv, acc.y * iv, acc.z * iv, acc.w * iv);
    *(float4*)(ms + (size_t)node * D + lane * 4) = o;
}

// ---------------- layer 0: writes fp16 h1 ----------------
__global__ void __launch_bounds__(256, 3) layer0_kernel(
    const __half* __restrict__ hin,
    const float* __restrict__ m0,
    const float* __restrict__ m1,
    const float* __restrict__ Wl,
    const float* __restrict__ Wr,
    const float* __restrict__ bl,
    __half* __restrict__ hout)
{
    __shared__ float Ws[192 * 64];
    const int tid = threadIdx.x;

    #pragma unroll
    for (int i = 0; i < 4; i++) {
        int idx = (tid + i * 256) * 4;
        float4 a = *(const float4*)(Wl + idx);
        float4 b = *(const float4*)(Wl + 4096 + idx);
        float4 c = *(const float4*)(Wr + idx);
        float4 d = *(const float4*)(Wr + 4096 + idx);
        *(float4*)(Ws + idx)        = a;
        *(float4*)(Ws + 4096 + idx) = b;
        *(float4*)(Ws + 8192 + idx) = make_float4(c.x + d.x, c.y + d.y, c.z + d.z, c.w + d.w);
    }
    __syncthreads();

    const int c0      = (tid & 15) * 4;
    const int rowBase = blockIdx.x * 128 + (tid >> 4) * 8;

    float acc[8][4];
    {
        float4 b0 = *(const float4*)(bl + c0);
        float4 b1 = *(const float4*)(bl + 64 + c0);
        float s0 = b0.x + b1.x, s1 = b0.y + b1.y, s2 = b0.z + b1.z, s3 = b0.w + b1.w;
        #pragma unroll
        for (int i = 0; i < 8; i++) { acc[i][0] = s0; acc[i][1] = s1; acc[i][2] = s2; acc[i][3] = s3; }
    }

    // segments 0,1: fp32 means
    #pragma unroll
    for (int s = 0; s < 2; s++) {
        const float* Arow = (s == 0 ? m0 : m1) + (size_t)rowBase * D;
        const float* Wseg = Ws + s * 4096;
        #pragma unroll 1
        for (int k4 = 0; k4 < 16; k4++) {
            float4 bv0 = *(const float4*)(Wseg + (k4 * 4 + 0) * 64 + c0);
            float4 bv1 = *(const float4*)(Wseg + (k4 * 4 + 1) * 64 + c0);
            float4 bv2 = *(const float4*)(Wseg + (k4 * 4 + 2) * 64 + c0);
            float4 bv3 = *(const float4*)(Wseg + (k4 * 4 + 3) * 64 + c0);
            #pragma unroll
            for (int i = 0; i < 8; i++) {
                float4 av = *(const float4*)(Arow + i * D + k4 * 4);
                acc[i][0] += av.x * bv0.x + av.y * bv1.x + av.z * bv2.x + av.w * bv3.x;
                acc[i][1] += av.x * bv0.y + av.y * bv1.y + av.z * bv2.y + av.w * bv3.y;
                acc[i][2] += av.x * bv0.z + av.y * bv1.z + av.z * bv2.z + av.w * bv3.z;
                acc[i][3] += av.x * bv0.w + av.y * bv1.w + av.z * bv2.w + av.w * bv3.w;
            }
        }
    }
    // segment 2: fp16 self features
    {
        const __half* Arow = hin + (size_t)rowBase * D;
        const float* Wseg = Ws + 8192;
        #pragma unroll 1
        for (int k4 = 0; k4 < 16; k4++) {
            float4 bv0 = *(const float4*)(Wseg + (k4 * 4 + 0) * 64 + c0);
            float4 bv1 = *(const float4*)(Wseg + (k4 * 4 + 1) * 64 + c0);
            float4 bv2 = *(const float4*)(Wseg + (k4 * 4 + 2) * 64 + c0);
            float4 bv3 = *(const float4*)(Wseg + (k4 * 4 + 3) * 64 + c0);
            #pragma unroll
            for (int i = 0; i < 8; i++) {
                uint2 u = *reinterpret_cast<const uint2*>(Arow + i * D + k4 * 4);
                __half2 h01 = *reinterpret_cast<__half2*>(&u.x);
                __half2 h23 = *reinterpret_cast<__half2*>(&u.y);
                float2 f01 = __half22float2(h01);
                float2 f23 = __half22float2(h23);
                acc[i][0] += f01.x * bv0.x + f01.y * bv1.x + f23.x * bv2.x + f23.y * bv3.x;
                acc[i][1] += f01.x * bv0.y + f01.y * bv1.y + f23.x * bv2.y + f23.y * bv3.y;
                acc[i][2] += f01.x * bv0.z + f01.y * bv1.z + f23.x * bv2.z + f23.y * bv3.z;
                acc[i][3] += f01.x * bv0.w + f01.y * bv1.w + f23.x * bv2.w + f23.y * bv3.w;
            }
        }
    }

    __half* orow = hout + (size_t)rowBase * D + c0;
    #pragma unroll
    for (int i = 0; i < 8; i++) {
        __half2 p0 = __floats2half2_rn(fmaxf(acc[i][0], 0.f), fmaxf(acc[i][1], 0.f));
        __half2 p1 = __floats2half2_rn(fmaxf(acc[i][2], 0.f), fmaxf(acc[i][3], 0.f));
        uint2 u;
        u.x = *reinterpret_cast<unsigned int*>(&p0);
        u.y = *reinterpret_cast<unsigned int*>(&p1);
        *reinterpret_cast<uint2*>(orow + i * D) = u;
    }
}

// ---------------- layer 1 fused with final projection: writes fp32 out[N,32] ----------------
__global__ void __launch_bounds__(256, 3) layer1_fused_kernel(
    const __half* __restrict__ hin,
    const float* __restrict__ m0,
    const float* __restrict__ m1,
    const float* __restrict__ Wl,
    const float* __restrict__ Wr,
    const float* __restrict__ bl,
    const float* __restrict__ linW,   // [64][32]
    const float* __restrict__ linb,   // [32]
    float* __restrict__ out)
{
    __shared__ float Ws[192 * 64];    // phase 1: weights; phase 2: tile[128*64] + linW[64*32]
    const int tid = threadIdx.x;

    #pragma unroll
    for (int i = 0; i < 4; i++) {
        int idx = (tid + i * 256) * 4;
        float4 a = *(const float4*)(Wl + idx);
        float4 b = *(const float4*)(Wl + 4096 + idx);
        float4 c = *(const float4*)(Wr + idx);
        float4 d = *(const float4*)(Wr + 4096 + idx);
        *(float4*)(Ws + idx)        = a;
        *(float4*)(Ws + 4096 + idx) = b;
        *(float4*)(Ws + 8192 + idx) = make_float4(c.x + d.x, c.y + d.y, c.z + d.z, c.w + d.w);
    }
    __syncthreads();

    const int c0      = (tid & 15) * 4;
    const int rowLoc  = (tid >> 4) * 8;
    const int rowBase = blockIdx.x * 128 + rowLoc;

    float acc[8][4];
    {
        float4 b0 = *(const float4*)(bl + c0);
        float4 b1 = *(const float4*)(bl + 64 + c0);
        float s0 = b0.x + b1.x, s1 = b0.y + b1.y, s2 = b0.z + b1.z, s3 = b0.w + b1.w;
        #pragma unroll
        for (int i = 0; i < 8; i++) { acc[i][0] = s0; acc[i][1] = s1; acc[i][2] = s2; acc[i][3] = s3; }
    }

    #pragma unroll
    for (int s = 0; s < 2; s++) {
        const float* Arow = (s == 0 ? m0 : m1) + (size_t)rowBase * D;
        const float* Wseg = Ws + s * 4096;
        #pragma unroll 1
        for (int k4 = 0; k4 < 16; k4++) {
            float4 bv0 = *(const float4*)(Wseg + (k4 * 4 + 0) * 64 + c0);
            float4 bv1 = *(const float4*)(Wseg + (k4 * 4 + 1) * 64 + c0);
            float4 bv2 = *(const float4*)(Wseg + (k4 * 4 + 2) * 64 + c0);
            float4 bv3 = *(const float4*)(Wseg + (k4 * 4 + 3) * 64 + c0);
            #pragma unroll
            for (int i = 0; i < 8; i++) {
                float4 av = *(const float4*)(Arow + i * D + k4 * 4);
                acc[i][0] += av.x * bv0.x + av.y * bv1.x + av.z * bv2.x + av.w * bv3.x;
                acc[i][1] += av.x * bv0.y + av.y * bv1.y + av.z * bv2.y + av.w * bv3.y;
                acc[i][2] += av.x * bv0.z + av.y * bv1.z + av.z * bv2.z + av.w * bv3.z;
                acc[i][3] += av.x * bv0.w + av.y * bv1.w + av.z * bv2.w + av.w * bv3.w;
            }
        }
    }
    {
        const __half* Arow = hin + (size_t)rowBase * D;
        const float* Wseg = Ws + 8192;
        #pragma unroll 1
        for (int k4 = 0; k4 < 16; k4++) {
            float4 bv0 = *(const float4*)(Wseg + (k4 * 4 + 0) * 64 + c0);
            float4 bv1 = *(const float4*)(Wseg + (k4 * 4 + 1) * 64 + c0);
            float4 bv2 = *(const float4*)(Wseg + (k4 * 4 + 2) * 64 + c0);
            float4 bv3 = *(const float4*)(Wseg + (k4 * 4 + 3) * 64 + c0);
            #pragma unroll
            for (int i = 0; i < 8; i++) {
                uint2 u = *reinterpret_cast<const uint2*>(Arow + i * D + k4 * 4);
                __half2 h01 = *reinterpret_cast<__half2*>(&u.x);
                __half2 h23 = *reinterpret_cast<__half2*>(&u.y);
                float2 f01 = __half22float2(h01);
                float2 f23 = __half22float2(h23);
                acc[i][0] += f01.x * bv0.x + f01.y * bv1.x + f23.x * bv2.x + f23.y * bv3.x;
                acc[i][1] += f01.x * bv0.y + f01.y * bv1.y + f23.x * bv2.y + f23.y * bv3.y;
                acc[i][2] += f01.x * bv0.z + f01.y * bv1.z + f23.x * bv2.z + f23.y * bv3.z;
                acc[i][3] += f01.x * bv0.w + f01.y * bv1.w + f23.x * bv2.w + f23.y * bv3.w;
            }
        }
    }

    // ---- phase 2: h2 tile -> smem, multiply by linW, write out ----
    __syncthreads();                               // everyone done reading weight smem
    float* tile = Ws;                              // [128][64] = 32KB
    float* Wf   = Ws + 128 * 64;                   // [64][32]  =  8KB
    #pragma unroll
    for (int i = 0; i < 8; i++) {
        float4 o;
        o.x = fmaxf(acc[i][0], 0.f);
        o.y = fmaxf(acc[i][1], 0.f);
        o.z = fmaxf(acc[i][2], 0.f);
        o.w = fmaxf(acc[i][3], 0.f);
        *(float4*)(tile + (rowLoc + i) * 64 + c0) = o;
    }
    #pragma unroll
    for (int i = 0; i < 2; i++) {
        int idx = (tid + i * 256) * 4;             // 512 float4 = 2048 floats
        *(float4*)(Wf + idx) = *(const float4*)(linW + idx);
    }
    __syncthreads();

    const int c0f = (tid & 7) * 4;                 // output cols
    const int rl  = (tid >> 3) * 4;                // local rows 0..127
    float4 bv = *(const float4*)(linb + c0f);
    float f0[4], f1[4], f2[4], f3[4];
    #pragma unroll
    for (int i = 0; i < 4; i++) { f0[i] = bv.x; f1[i] = bv.y; f2[i] = bv.z; f3[i] = bv.w; }

    #pragma unroll 8
    for (int k = 0; k < 64; k++) {
        float4 w = *(const float4*)(Wf + k * 32 + c0f);
        #pragma unroll
        for (int i = 0; i < 4; i++) {
            float a = tile[(rl + i) * 64 + k];
            f0[i] += a * w.x; f1[i] += a * w.y; f2[i] += a * w.z; f3[i] += a * w.w;
        }
    }

    #pragma unroll
    for (int i = 0; i < 4; i++) {
        int r = blockIdx.x * 128 + rl + i;
        if (r < N_NODES) {
            *(float4*)(out + (size_t)r * D_OUT + c0f) = make_float4(f0[i], f1[i], f2[i], f3[i]);
        }
    }
}

// ---------------- launch ----------------
extern "C" void kernel_launch(void* const* d_in, const int* in_sizes, int n_in,
                              void* d_out, int out_size) {
    const float* x    = (const float*)d_in[0];
    const int*   ei0  = (const int*)  d_in[1];
    const int*   ei1  = (const int*)  d_in[2];
    const float* Wl   = (const float*)d_in[3];
    const float* Wr   = (const float*)d_in[4];
    const float* bl   = (const float*)d_in[5];
    const float* linW = (const float*)d_in[6];
    const float* linb = (const float*)d_in[7];
    float* out = (float*)d_out;

    void *p_xh, *p_h1, *p_ms0, *p_ms1, *p_deg;
    cudaGetSymbolAddress(&p_xh,  g_xh);
    cudaGetSymbolAddress(&p_h1,  g_h1);
    cudaGetSymbolAddress(&p_ms0, g_ms0);
    cudaGetSymbolAddress(&p_ms1, g_ms1);
    cudaGetSymbolAddress(&p_deg, g_deg);

    const int gemmGrid = N_PAD / 128;              // 391
    const dim3 edgeGrid(N_EDGES / 256, 2);         // exact
    const dim3 scanGrid(NBLK_SCAN, 2);
    const dim3 gatherGrid(N_NODES / 16, 2);        // exact

    // fp16 input conversion (pad rows of g_xh remain zero from static init)
    cvt_x_kernel<<<N_NODES * D / 4 / 256, 256>>>(x);   // 3125 blocks, exact

    // CSR build
    cudaMemsetAsync(p_deg, 0, 2 * N_NODES * sizeof(int));
    deg_count_kernel<<<edgeGrid, 256>>>(ei0, ei1);
    block_reduce_kernel<<<scanGrid, 256>>>();
    scan_bsums_kernel<<<1, 256>>>();
    finalize_scan_kernel<<<scanGrid, 256>>>();
    fill_kernel<<<edgeGrid, 256>>>(ei0, ei1);

    // layer 0
    gather_kernel<<<gatherGrid, 256>>>((const __half*)p_xh);
    layer0_kernel<<<gemmGrid, 256>>>((const __half*)p_xh,
                                     (const float*)p_ms0, (const float*)p_ms1,
                                     Wl, Wr, bl, (__half*)p_h1);

    // layer 1 + final projection fused
    gather_kernel<<<gatherGrid, 256>>>((const __half*)p_h1);
    layer1_fused_kernel<<<gemmGrid, 256>>>((const __half*)p_h1,
                                           (const float*)p_ms0, (const float*)p_ms1,
                                           Wl + 2 * 64 * 64, Wr + 2 * 64 * 64, bl + 2 * 64,
                                           linW, linb, out);
}